// round 2
// baseline (speedup 1.0000x reference)
#include <cuda_runtime.h>

#define HH 64
#define WW 64
#define HW 4096
#define CING 128
#define COUTG 128
#define BB 8
#define K2C 9

// Scratch (no allocs allowed): offset-conv partials per cin-group, transposed conv weight.
__device__ float g_offp[4 * BB * 18 * HW];     // [g][b][ch(18)][h][w]  ~9.4 MB
__device__ float g_wT[K2C * CING * COUTG];     // [k][cin][o]           ~589 KB

// ---------------------------------------------------------------------------
// Kernel 0: transpose w_conv [o][cin][k] -> g_wT [k][cin][o]
// ---------------------------------------------------------------------------
__global__ void transpose_w_kernel(const float* __restrict__ w) {
    int idx = blockIdx.x * 256 + threadIdx.x;
    if (idx < K2C * CING * COUTG) {
        int o = idx & 127;
        int cin = (idx >> 7) & 127;
        int k = idx >> 14;
        g_wT[idx] = w[(o * CING + cin) * K2C + k];
    }
}

// ---------------------------------------------------------------------------
// Kernel 1: 3x3 offset conv, partial over cin groups of 32.
// grid: (4 spatial tiles of 32x32, b=8, cg=4), 256 threads, 4 px/thread.
// ---------------------------------------------------------------------------
__global__ __launch_bounds__(256) void offset_conv_kernel(
        const float* __restrict__ x, const float* __restrict__ wofs) {
    const int tile = blockIdx.x;
    const int b = blockIdx.y;
    const int cg = blockIdx.z;
    const int ty0 = (tile >> 1) * 32, tx0 = (tile & 1) * 32;
    const int tid = threadIdx.x;

    __shared__ float ws_s[32][162];   // [cin_local][oc*9+kk]
    __shared__ float patch[34][34];

    for (int idx = tid; idx < 32 * 162; idx += 256) {
        int cl = idx / 162, r = idx - cl * 162;
        ws_s[cl][r] = wofs[((r / 9) * CING + cg * 32 + cl) * 9 + (r % 9)];
    }

    float acc[18][4];
#pragma unroll
    for (int oc = 0; oc < 18; ++oc)
#pragma unroll
        for (int i = 0; i < 4; ++i) acc[oc][i] = 0.f;

    const int pc = tid & 31;
    const int pr0 = tid >> 5;

    for (int cl = 0; cl < 32; ++cl) {
        const float* xp = x + (b * CING + cg * 32 + cl) * HW;
        __syncthreads();
        for (int idx = tid; idx < 34 * 34; idx += 256) {
            int r = idx / 34, c = idx - r * 34;
            int y = ty0 - 1 + r, xx = tx0 - 1 + c;
            float v = 0.f;
            if (y >= 0 && y < HH && xx >= 0 && xx < WW) v = xp[y * WW + xx];
            patch[r][c] = v;
        }
        __syncthreads();
#pragma unroll
        for (int ky = 0; ky < 3; ++ky)
#pragma unroll
        for (int kx = 0; kx < 3; ++kx) {
            const int kk = ky * 3 + kx;
            float v0 = patch[pr0 +  0 + ky][pc + kx];
            float v1 = patch[pr0 +  8 + ky][pc + kx];
            float v2 = patch[pr0 + 16 + ky][pc + kx];
            float v3 = patch[pr0 + 24 + ky][pc + kx];
#pragma unroll
            for (int oc = 0; oc < 18; ++oc) {
                float wv = ws_s[cl][oc * 9 + kk];
                acc[oc][0] += wv * v0;
                acc[oc][1] += wv * v1;
                acc[oc][2] += wv * v2;
                acc[oc][3] += wv * v3;
            }
        }
    }

    float* op = g_offp + (cg * BB + b) * 18 * HW;
#pragma unroll
    for (int oc = 0; oc < 18; ++oc)
#pragma unroll
        for (int i = 0; i < 4; ++i) {
            int y = ty0 + pr0 + 8 * i;
            op[oc * HW + y * WW + tx0 + pc] = acc[oc][i];
        }
}

// ---------------------------------------------------------------------------
// Kernel 2: deformable conv as implicit GEMM.
// grid: (h/2 = 32, b = 8). Block: 256 threads, C tile = 128 out x 128 px
// (2 image rows). ck = k*128+cin looped as 9 k x 4 cin-chunks of 32.
// ---------------------------------------------------------------------------
__global__ __launch_bounds__(256) void deform_kernel(
        const float* __restrict__ x, float* __restrict__ out) {
    const int h0 = blockIdx.x * 2;
    const int b = blockIdx.y;
    const int tid = threadIdx.x;

    __shared__ float Ws[32][128];          // [cc][o]
    __shared__ float Vs[32][128];          // [cc][p]  p = rr*64 + w
    __shared__ float w00s[128], w01s[128], w10s[128], w11s[128];
    __shared__ int   o00s[128], o01s[128], o10s[128], o11s[128];

    float C[8][8];
#pragma unroll
    for (int r = 0; r < 8; ++r)
#pragma unroll
        for (int c = 0; c < 8; ++c) C[r][c] = 0.f;

    const int i = tid >> 4;   // 0..15 -> o block of 8
    const int j = tid & 15;   // 0..15 -> w block of 4 (both rows)

    for (int k = 0; k < 9; ++k) {
        // ---- per-(k, pixel) bilinear params (shared across all cin) ----
        if (tid < 128) {
            int p = tid, rr = p >> 6, w = p & 63;
            int h = h0 + rr;
            float dy = 0.f, dx = 0.f;
#pragma unroll
            for (int g = 0; g < 4; ++g) {
                const float* op = g_offp + (((g * BB + b) * 18 + 2 * k) * HH + h) * WW;
                dy += op[w];
                dx += op[HW + w];
            }
            float py = (float)(h - 1 + k / 3) + dy;
            float px = (float)(w - 1 + k % 3) + dx;
            float y0 = floorf(py), x0 = floorf(px);
            float fy = py - y0, fx = px - x0;
            float gy = 1.f - fy, gx = 1.f - fx;
            bool vy0 = (y0 >= 0.f) && (y0 < 64.f);
            bool vy1 = (y0 + 1.f >= 0.f) && (y0 + 1.f < 64.f);
            bool vx0 = (x0 >= 0.f) && (x0 < 64.f);
            bool vx1 = (x0 + 1.f >= 0.f) && (x0 + 1.f < 64.f);
            int yi0 = (int)fminf(fmaxf(y0, 0.f), 63.f);
            int yi1 = (int)fminf(fmaxf(y0 + 1.f, 0.f), 63.f);
            int xi0 = (int)fminf(fmaxf(x0, 0.f), 63.f);
            int xi1 = (int)fminf(fmaxf(x0 + 1.f, 0.f), 63.f);
            w00s[p] = (vy0 && vx0) ? gy * gx : 0.f;
            w01s[p] = (vy0 && vx1) ? gy * fx : 0.f;
            w10s[p] = (vy1 && vx0) ? fy * gx : 0.f;
            w11s[p] = (vy1 && vx1) ? fy * fx : 0.f;
            o00s[p] = yi0 * WW + xi0;
            o01s[p] = yi0 * WW + xi1;
            o10s[p] = yi1 * WW + xi0;
            o11s[p] = yi1 * WW + xi1;
        }

        for (int cg = 0; cg < 4; ++cg) {
            __syncthreads();   // params ready / previous compute done

            // stage W chunk [32 cc][128 o] (pre-transposed, coalesced float4)
            const float4* wsrc = (const float4*)(g_wT + (k * CING + cg * 32) * COUTG);
            float4* wdst = (float4*)&Ws[0][0];
#pragma unroll
            for (int t = 0; t < 4; ++t) wdst[tid + 256 * t] = wsrc[tid + 256 * t];

            // gather V chunk [32 cc][128 p] via bilinear taps
            {
                int p = tid & 127, ccs = tid >> 7;
                float a00 = w00s[p], a01 = w01s[p], a10 = w10s[p], a11 = w11s[p];
                int q00 = o00s[p], q01 = o01s[p], q10 = o10s[p], q11 = o11s[p];
                const float* xb = x + (b * CING + cg * 32) * HW;
#pragma unroll
                for (int cc = ccs; cc < 32; cc += 2) {
                    const float* xc = xb + cc * HW;
                    Vs[cc][p] = a00 * xc[q00] + a01 * xc[q01]
                              + a10 * xc[q10] + a11 * xc[q11];
                }
            }
            __syncthreads();

            // 8x8 register-tile GEMM over the 32-wide chunk
#pragma unroll 8
            for (int cc = 0; cc < 32; ++cc) {
                float4 w0 = *(const float4*)&Ws[cc][i * 8];
                float4 w1 = *(const float4*)&Ws[cc][i * 8 + 4];
                float4 v0 = *(const float4*)&Vs[cc][j * 4];         // row h0
                float4 v1 = *(const float4*)&Vs[cc][64 + j * 4];    // row h0+1
                float wr[8] = {w0.x, w0.y, w0.z, w0.w, w1.x, w1.y, w1.z, w1.w};
                float vc[8] = {v0.x, v0.y, v0.z, v0.w, v1.x, v1.y, v1.z, v1.w};
#pragma unroll
                for (int r = 0; r < 8; ++r)
#pragma unroll
                    for (int c = 0; c < 8; ++c)
                        C[r][c] += wr[r] * vc[c];
            }
        }
    }

    // epilogue: out[b][o][h][w]
#pragma unroll
    for (int r = 0; r < 8; ++r) {
        int o = i * 8 + r;
        float* ob = out + ((b * COUTG + o) * HH + h0) * WW + j * 4;
        *(float4*)ob        = make_float4(C[r][0], C[r][1], C[r][2], C[r][3]);
        *(float4*)(ob + WW) = make_float4(C[r][4], C[r][5], C[r][6], C[r][7]);
    }
}

// ---------------------------------------------------------------------------
extern "C" void kernel_launch(void* const* d_in, const int* in_sizes, int n_in,
                              void* d_out, int out_size) {
    const float* x        = (const float*)d_in[0];
    const float* w_offset = (const float*)d_in[1];
    const float* w_conv   = (const float*)d_in[2];
    float* out = (float*)d_out;
    (void)in_sizes; (void)n_in; (void)out_size;

    transpose_w_kernel<<<(K2C * CING * COUTG + 255) / 256, 256>>>(w_conv);
    offset_conv_kernel<<<dim3(4, 8, 4), 256>>>(x, w_offset);
    deform_kernel<<<dim3(32, 8), 256>>>(x, out);
}

// round 5
// speedup vs baseline: 1.3092x; 1.3092x over previous
#include <cuda_runtime.h>
#include <cstdint>

#define HH 64
#define WW 64
#define HW 4096
#define CING 128
#define COUTG 128
#define BB 8
#define K2C 9
#define KK_TOT (K2C * CING)   // 1152

// ---- device scratch (no allocs allowed) -----------------------------------
__device__ float g_offp[4 * BB * 18 * HW];        // offset-conv partials  9.4 MB
__device__ float g_wT[K2C * CING * COUTG];        // [kk][o]               0.6 MB
__device__ float4 g_pw[BB * K2C * HW];            // bilinear weights      4.7 MB
__device__ int4   g_po[BB * K2C * HW];            // tap offsets           4.7 MB
__device__ float  g_V[BB * KK_TOT * HW];          // gathered V          151   MB

// ---------------------------------------------------------------------------
// Kernel 0: transpose w_conv [o][cin][k] -> g_wT [kk=k*128+cin][o]
// ---------------------------------------------------------------------------
__global__ void transpose_w_kernel(const float* __restrict__ w) {
    int idx = blockIdx.x * 256 + threadIdx.x;
    if (idx < K2C * CING * COUTG) {
        int o = idx & 127;
        int cin = (idx >> 7) & 127;
        int k = idx >> 14;
        g_wT[idx] = w[(o * CING + cin) * K2C + k];
    }
}

// ---------------------------------------------------------------------------
// Kernel 1: 3x3 offset conv, partial over 4 cin groups of 32.
// ---------------------------------------------------------------------------
__global__ __launch_bounds__(256) void offset_conv_kernel(
        const float* __restrict__ x, const float* __restrict__ wofs) {
    const int tile = blockIdx.x;
    const int b = blockIdx.y;
    const int cg = blockIdx.z;
    const int ty0 = (tile >> 1) * 32, tx0 = (tile & 1) * 32;
    const int tid = threadIdx.x;

    __shared__ float ws_s[32][162];
    __shared__ float patch[34][34];

    for (int idx = tid; idx < 32 * 162; idx += 256) {
        int cl = idx / 162, r = idx - cl * 162;
        ws_s[cl][r] = wofs[((r / 9) * CING + cg * 32 + cl) * 9 + (r % 9)];
    }

    float acc[18][4];
#pragma unroll
    for (int oc = 0; oc < 18; ++oc)
#pragma unroll
        for (int i = 0; i < 4; ++i) acc[oc][i] = 0.f;

    const int pc = tid & 31;
    const int pr0 = tid >> 5;

    for (int cl = 0; cl < 32; ++cl) {
        const float* xp = x + (b * CING + cg * 32 + cl) * HW;
        __syncthreads();
        for (int idx = tid; idx < 34 * 34; idx += 256) {
            int r = idx / 34, c = idx - r * 34;
            int y = ty0 - 1 + r, xx = tx0 - 1 + c;
            float v = 0.f;
            if (y >= 0 && y < HH && xx >= 0 && xx < WW) v = xp[y * WW + xx];
            patch[r][c] = v;
        }
        __syncthreads();
#pragma unroll
        for (int ky = 0; ky < 3; ++ky)
#pragma unroll
        for (int kx = 0; kx < 3; ++kx) {
            const int kk = ky * 3 + kx;
            float v0 = patch[pr0 +  0 + ky][pc + kx];
            float v1 = patch[pr0 +  8 + ky][pc + kx];
            float v2 = patch[pr0 + 16 + ky][pc + kx];
            float v3 = patch[pr0 + 24 + ky][pc + kx];
#pragma unroll
            for (int oc = 0; oc < 18; ++oc) {
                float wv = ws_s[cl][oc * 9 + kk];
                acc[oc][0] += wv * v0;
                acc[oc][1] += wv * v1;
                acc[oc][2] += wv * v2;
                acc[oc][3] += wv * v3;
            }
        }
    }

    float* op = g_offp + (cg * BB + b) * 18 * HW;
#pragma unroll
    for (int oc = 0; oc < 18; ++oc)
#pragma unroll
        for (int i = 0; i < 4; ++i) {
            int y = ty0 + pr0 + 8 * i;
            op[oc * HW + y * WW + tx0 + pc] = acc[oc][i];
        }
}

// ---------------------------------------------------------------------------
// Kernel 2: bilinear params per (b, k, px).
// ---------------------------------------------------------------------------
__global__ __launch_bounds__(256) void param_kernel() {
    const int k = blockIdx.x;
    const int b = blockIdx.y;
    const int tid = threadIdx.x;
    const int ky = k / 3, kx = k % 3;

#pragma unroll 4
    for (int i = 0; i < 16; ++i) {
        int px = i * 256 + tid;
        int h = px >> 6, w = px & 63;

        float dy = 0.f, dx = 0.f;
#pragma unroll
        for (int g = 0; g < 4; ++g) {
            const float* op = g_offp + ((g * BB + b) * 18 + 2 * k) * HW;
            dy += op[px];
            dx += op[HW + px];
        }
        float py = (float)(h - 1 + ky) + dy;
        float pxx = (float)(w - 1 + kx) + dx;
        float y0 = floorf(py), x0 = floorf(pxx);
        float fy = py - y0, fx = pxx - x0;
        float gy = 1.f - fy, gx = 1.f - fx;
        bool vy0 = (y0 >= 0.f) && (y0 < 64.f);
        bool vy1 = (y0 + 1.f >= 0.f) && (y0 + 1.f < 64.f);
        bool vx0 = (x0 >= 0.f) && (x0 < 64.f);
        bool vx1 = (x0 + 1.f >= 0.f) && (x0 + 1.f < 64.f);
        int yi0 = (int)fminf(fmaxf(y0, 0.f), 63.f);
        int yi1 = (int)fminf(fmaxf(y0 + 1.f, 0.f), 63.f);
        int xi0 = (int)fminf(fmaxf(x0, 0.f), 63.f);
        int xi1 = (int)fminf(fmaxf(x0 + 1.f, 0.f), 63.f);

        float4 wq;
        wq.x = (vy0 && vx0) ? gy * gx : 0.f;
        wq.y = (vy0 && vx1) ? gy * fx : 0.f;
        wq.z = (vy1 && vx0) ? fy * gx : 0.f;
        wq.w = (vy1 && vx1) ? fy * fx : 0.f;
        int4 oq;
        oq.x = yi0 * WW + xi0;
        oq.y = yi0 * WW + xi1;
        oq.z = yi1 * WW + xi0;
        oq.w = yi1 * WW + xi1;

        g_pw[(b * K2C + k) * HW + px] = wq;
        g_po[(b * K2C + k) * HW + px] = oq;
    }
}

// ---------------------------------------------------------------------------
// Kernel 3: gather. 8 channels resident in SMEM; random bilinear taps hit the
// SMEM crossbar. Zero-weight taps skipped. Writes V[b][k][cin][px] coalesced.
// ---------------------------------------------------------------------------
__global__ __launch_bounds__(256) void gather_kernel(const float* __restrict__ x) {
    extern __shared__ float sx[];   // 8 * 4096 floats = 128 KB
    const int cg = blockIdx.x;      // 0..15
    const int b = blockIdx.y;
    const int tid = threadIdx.x;

    const float4* src = (const float4*)(x + (b * CING + cg * 8) * HW);
    float4* dst = (float4*)sx;
#pragma unroll
    for (int t = 0; t < 32; ++t) dst[tid + 256 * t] = src[tid + 256 * t];
    __syncthreads();

    for (int k = 0; k < K2C; ++k) {
        const float4* pw = g_pw + (b * K2C + k) * HW;
        const int4*   po = g_po + (b * K2C + k) * HW;
        float* vout = g_V + ((b * K2C + k) * CING + cg * 8) * HW;
#pragma unroll 2
        for (int i = 0; i < 16; ++i) {
            int px = i * 256 + tid;
            float4 wq = pw[px];
            int4 oq = po[px];
#pragma unroll
            for (int cc = 0; cc < 8; ++cc) {
                const float* ch = sx + cc * HW;
                float acc = 0.f;
                if (wq.x != 0.f) acc += wq.x * ch[oq.x];
                if (wq.y != 0.f) acc += wq.y * ch[oq.y];
                if (wq.z != 0.f) acc += wq.z * ch[oq.z];
                if (wq.w != 0.f) acc += wq.w * ch[oq.w];
                vout[cc * HW + px] = acc;
            }
        }
    }
}

// ---------------------------------------------------------------------------
// Kernel 4: dense GEMM  out[b][o][px] = sum_kk W[kk][o] * V[b][kk][px]
// 128x128 tile, K-chunks of 16, cp.async double buffer, packed f32x2 FMA
// (b64 register class — "l" constraints).
// ---------------------------------------------------------------------------
__device__ __forceinline__ void cpa16(void* smem_dst, const void* gsrc) {
    uint32_t d = (uint32_t)__cvta_generic_to_shared(smem_dst);
    asm volatile("cp.async.cg.shared.global [%0], [%1], 16;" :: "r"(d), "l"(gsrc));
}
__device__ __forceinline__ void cpa_commit() {
    asm volatile("cp.async.commit_group;");
}
__device__ __forceinline__ void cpa_wait1() {
    asm volatile("cp.async.wait_group 1;");
}
__device__ __forceinline__ void cpa_wait0() {
    asm volatile("cp.async.wait_group 0;");
}
__device__ __forceinline__ unsigned long long pk2(float w) {
    unsigned long long d;
    asm("mov.b64 %0, {%1, %1};" : "=l"(d) : "f"(w));
    return d;
}
__device__ __forceinline__ void fma2(unsigned long long& d,
                                     unsigned long long a, unsigned long long b) {
    asm("fma.rn.f32x2 %0, %1, %2, %0;" : "+l"(d) : "l"(a), "l"(b));
}

__global__ __launch_bounds__(256) void gemm_kernel(float* __restrict__ out) {
    const int px0 = blockIdx.x * 128;
    const int b = blockIdx.y;
    const int tid = threadIdx.x;

    __shared__ float Ws[2][16][128];
    __shared__ float Vs[2][16][128];

    const int i = tid >> 4;    // 0..15 -> o block of 8
    const int j = tid & 15;    // 0..15 -> px cols j*4 and 64+j*4

    unsigned long long C2[8][4];
#pragma unroll
    for (int r = 0; r < 8; ++r)
#pragma unroll
        for (int c = 0; c < 4; ++c) C2[r][c] = 0ull;

    const int lr = tid >> 5;        // 0..7 stage row
    const int lc = (tid & 31) * 4;  // float4 col

    // prologue: stage chunk 0
    {
        const float* wsrc = g_wT;
        const float* vsrc = g_V + (size_t)(b * KK_TOT) * HW + px0;
        cpa16(&Ws[0][lr][lc],     wsrc + lr * 128 + lc);
        cpa16(&Ws[0][lr + 8][lc], wsrc + (lr + 8) * 128 + lc);
        cpa16(&Vs[0][lr][lc],     vsrc + (size_t)lr * HW + lc);
        cpa16(&Vs[0][lr + 8][lc], vsrc + (size_t)(lr + 8) * HW + lc);
        cpa_commit();
    }

    const int NCH = KK_TOT / 16;   // 72
    for (int s = 0; s < NCH; ++s) {
        if (s + 1 < NCH) {
            int kk0 = (s + 1) * 16;
            int nb = (s + 1) & 1;
            const float* wsrc = g_wT + kk0 * 128;
            const float* vsrc = g_V + (size_t)(b * KK_TOT + kk0) * HW + px0;
            cpa16(&Ws[nb][lr][lc],     wsrc + lr * 128 + lc);
            cpa16(&Ws[nb][lr + 8][lc], wsrc + (lr + 8) * 128 + lc);
            cpa16(&Vs[nb][lr][lc],     vsrc + (size_t)lr * HW + lc);
            cpa16(&Vs[nb][lr + 8][lc], vsrc + (size_t)(lr + 8) * HW + lc);
            cpa_commit();
            cpa_wait1();
        } else {
            cpa_wait0();
        }
        __syncthreads();

        const int bf = s & 1;
#pragma unroll
        for (int kk = 0; kk < 16; ++kk) {
            ulonglong2 v0 = *(const ulonglong2*)&Vs[bf][kk][j * 4];
            ulonglong2 v1 = *(const ulonglong2*)&Vs[bf][kk][64 + j * 4];
            float4 wa = *(const float4*)&Ws[bf][kk][i * 8];
            float4 wb = *(const float4*)&Ws[bf][kk][i * 8 + 4];
            float wr[8] = {wa.x, wa.y, wa.z, wa.w, wb.x, wb.y, wb.z, wb.w};
#pragma unroll
            for (int r = 0; r < 8; ++r) {
                unsigned long long w2 = pk2(wr[r]);
                fma2(C2[r][0], w2, v0.x);
                fma2(C2[r][1], w2, v0.y);
                fma2(C2[r][2], w2, v1.x);
                fma2(C2[r][3], w2, v1.y);
            }
        }
        __syncthreads();
    }

    // epilogue: f32x2 pairs are bit-identical to 2 consecutive floats
#pragma unroll
    for (int r = 0; r < 8; ++r) {
        int o = i * 8 + r;
        float* ob = out + (size_t)(b * COUTG + o) * HW + px0 + j * 4;
        *(ulonglong2*)ob        = make_ulonglong2(C2[r][0], C2[r][1]);
        *(ulonglong2*)(ob + 64) = make_ulonglong2(C2[r][2], C2[r][3]);
    }
}

// ---------------------------------------------------------------------------
extern "C" void kernel_launch(void* const* d_in, const int* in_sizes, int n_in,
                              void* d_out, int out_size) {
    const float* x        = (const float*)d_in[0];
    const float* w_offset = (const float*)d_in[1];
    const float* w_conv   = (const float*)d_in[2];
    float* out = (float*)d_out;
    (void)in_sizes; (void)n_in; (void)out_size;

    cudaFuncSetAttribute(gather_kernel,
                         cudaFuncAttributeMaxDynamicSharedMemorySize, 131072);

    transpose_w_kernel<<<(K2C * CING * COUTG + 255) / 256, 256>>>(w_conv);
    offset_conv_kernel<<<dim3(4, 8, 4), 256>>>(x, w_offset);
    param_kernel<<<dim3(K2C, BB), 256>>>();
    gather_kernel<<<dim3(16, BB), 256, 131072>>>(x);
    gemm_kernel<<<dim3(32, BB), 256>>>(out);
}